// round 1
// baseline (speedup 1.0000x reference)
#include <cuda_runtime.h>
#include <cstdint>

#define TILE 128

// Global accumulator (no cudaMalloc allowed). Zeroed by zero_k each launch so
// CUDA-graph replays are deterministic.
static __device__ double g_acc;

__device__ __forceinline__ float frsqrt_(float x) {
    float r; asm("rsqrt.approx.f32 %0, %1;" : "=f"(r) : "f"(x)); return r;
}
__device__ __forceinline__ float fsqrt_(float x) {
    float r; asm("sqrt.approx.f32 %0, %1;" : "=f"(r) : "f"(x)); return r;
}
__device__ __forceinline__ float frcp_(float x) {
    float r; asm("rcp.approx.f32 %0, %1;" : "=f"(r) : "f"(x)); return r;
}

// Quaternion (qw,qx,qy,qz), UNNORMALIZED (matches reference), to row-major R.
// u_R[j] = sum_i d_i * R[i*3+j]
__device__ __forceinline__ void quat_to_R(float qw, float qx, float qy, float qz,
                                          float* R) {
    float xx = qx * qx, yy = qy * qy, zz = qz * qz;
    float xy = qx * qy, xz = qx * qz, yz = qy * qz;
    float wx = qw * qx, wy = qw * qy, wz = qw * qz;
    R[0] = 1.0f - 2.0f * yy - 2.0f * zz;
    R[1] = 2.0f * xy - 2.0f * wz;
    R[2] = 2.0f * xz + 2.0f * wy;
    R[3] = 2.0f * xy + 2.0f * wz;
    R[4] = 1.0f - 2.0f * xx - 2.0f * zz;
    R[5] = 2.0f * yz - 2.0f * wx;
    R[6] = 2.0f * xz + 2.0f * wx;   // careful: R20 = 2qxqz - 2qyqw
    R[7] = 2.0f * yz + 2.0f * wx;
    R[8] = 1.0f - 2.0f * xx - 2.0f * yy;
    // fix R[5], R[6] per reference:
    // R12 = 2*qy*qz - 2*qx*qw  -> R[5]
    // R20 = 2*qx*qz - 2*qy*qw  -> R[6]
    R[6] = 2.0f * xz - 2.0f * wy;
}

__global__ void zero_k() { g_acc = 0.0; }

__global__ __launch_bounds__(TILE)
void pair_k(const float* __restrict__ xyz, const float* __restrict__ scales,
            const float* __restrict__ rot, const float* __restrict__ vel,
            int N, int T, int TP) {
    __shared__ float4 sh[TILE * 5];
    __shared__ float warp_sums[TILE / 32];

    int bx = blockIdx.x;
    int b  = bx / TP;
    int t  = bx - b * TP;
    // decode upper-triangular tile pair (i <= j)
    int i = 0;
    while (t >= T - i) { t -= T - i; i++; }
    int j = i + t;

    int tid = threadIdx.x;

    // ---- stage tile j into shared (one point per thread) ----
    {
        int m = j * TILE + tid;
        size_t p3 = (size_t)(b * N + m) * 3;
        size_t p4 = (size_t)(b * N + m) * 4;
        float x  = xyz[p3 + 0], y  = xyz[p3 + 1], z  = xyz[p3 + 2];
        float sx = scales[p3 + 0], sy = scales[p3 + 1], sz = scales[p3 + 2];
        float vx = vel[p3 + 0], vy = vel[p3 + 1], vz = vel[p3 + 2];
        float R[9];
        quat_to_R(rot[p4 + 0], rot[p4 + 1], rot[p4 + 2], rot[p4 + 3], R);
        sh[tid * 5 + 0] = make_float4(x, y, z, sx);
        sh[tid * 5 + 1] = make_float4(sy, sz, vx, vy);
        sh[tid * 5 + 2] = make_float4(vz, R[0], R[1], R[2]);
        sh[tid * 5 + 3] = make_float4(R[3], R[4], R[5], R[6]);
        sh[tid * 5 + 4] = make_float4(R[7], R[8], 0.0f, 0.0f);
    }

    // ---- own point n (registers) ----
    float xn, yn, zn, sxn, syn, szn, vxn, vyn, vzn;
    float Rn[9];
    {
        int n = i * TILE + tid;
        size_t p3 = (size_t)(b * N + n) * 3;
        size_t p4 = (size_t)(b * N + n) * 4;
        xn = xyz[p3 + 0]; yn = xyz[p3 + 1]; zn = xyz[p3 + 2];
        sxn = scales[p3 + 0]; syn = scales[p3 + 1]; szn = scales[p3 + 2];
        vxn = vel[p3 + 0]; vyn = vel[p3 + 1]; vzn = vel[p3 + 2];
        quat_to_R(rot[p4 + 0], rot[p4 + 1], rot[p4 + 2], rot[p4 + 3], Rn);
    }

    __syncthreads();

    float acc = 0.0f;

    #pragma unroll 4
    for (int m = 0; m < TILE; m++) {
        float4 p0 = sh[m * 5 + 0];
        float4 p1 = sh[m * 5 + 1];
        float4 p2 = sh[m * 5 + 2];
        float4 p3 = sh[m * 5 + 3];
        float4 p4 = sh[m * 5 + 4];

        float dx = xn - p0.x, dy = yn - p0.y, dz = zn - p0.z;
        float dd = dx * dx + dy * dy + dz * dz + 1e-8f;
        float inv = frsqrt_(dd);            // 1/dist

        // a = diff @ R_n, scaled by scales_m
        float a0 = (dx * Rn[0] + dy * Rn[3] + dz * Rn[6]) * p0.w;
        float a1 = (dx * Rn[1] + dy * Rn[4] + dz * Rn[7]) * p1.x;
        float a2 = (dx * Rn[2] + dy * Rn[5] + dz * Rn[8]) * p1.y;
        float s1 = a0 * a0 + a1 * a1 + a2 * a2;

        // bvec = diff @ R_m, scaled by scales_n
        float b0 = (dx * p2.y + dy * p3.x + dz * p3.w) * sxn; // Rm0, Rm3, Rm6
        float b1 = (dx * p2.z + dy * p3.y + dz * p4.x) * syn; // Rm1, Rm4, Rm7
        float b2 = (dx * p2.w + dy * p3.z + dz * p4.y) * szn; // Rm2, Rm5, Rm8
        float s2 = b0 * b0 + b1 * b1 + b2 * b2;

        // overlap = relu(r_total - dist) = inv * relu(sqrt(s1)+sqrt(s2) - dd)
        float relu_raw = fmaxf(fsqrt_(s1) + fsqrt_(s2) - dd, 0.0f);
        float ov = inv * relu_raw;

        // spectral repulsion: ov^2 / (1 + 0.1*ov)
        float spec = ov * ov * frcp_(1.0f + 0.1f * ov);

        // v_approach = (v_n - v_m) . direction
        float rvx = vxn - p1.z, rvy = vyn - p1.w, rvz = vzn - p2.x;
        float va = (rvx * dx + rvy * dy + rvz * dz) * inv;

        acc += spec + 0.1f * ov * fmaxf(-va, 0.0f);
    }

    // ---- block reduction ----
    #pragma unroll
    for (int off = 16; off > 0; off >>= 1)
        acc += __shfl_down_sync(0xFFFFFFFFu, acc, off);
    if ((tid & 31) == 0) warp_sums[tid >> 5] = acc;
    __syncthreads();
    if (tid == 0) {
        float s = 0.0f;
        #pragma unroll
        for (int w = 0; w < TILE / 32; w++) s += warp_sums[w];
        float weight = (i == j) ? 1.0f : 2.0f;   // symmetric counterpart
        atomicAdd(&g_acc, (double)(s * weight));
    }
}

__global__ void fin_k(float* out, double norm) {
    out[0] = (float)(g_acc / norm);
}

extern "C" void kernel_launch(void* const* d_in, const int* in_sizes, int n_in,
                              void* d_out, int out_size) {
    const float* xyz    = (const float*)d_in[0];
    const float* scales = (const float*)d_in[1];
    const float* rot    = (const float*)d_in[2];
    const float* vel    = (const float*)d_in[3];

    int BN = in_sizes[2] / 4;   // rotations: B*N*4
    int N  = 2048;
    if (BN % N != 0) N = BN;    // fallback (single batch)
    int B  = BN / N;

    int T  = N / TILE;          // 16 tiles per dim
    int TP = T * (T + 1) / 2;   // 136 upper-tri tile pairs per batch

    zero_k<<<1, 1>>>();
    pair_k<<<B * TP, TILE>>>(xyz, scales, rot, vel, N, T, TP);
    fin_k<<<1, 1>>>((float*)d_out, (double)B * (double)N * (double)N);
}

// round 2
// speedup vs baseline: 1.1920x; 1.1920x over previous
#include <cuda_runtime.h>
#include <cstdint>

#define TILE 128

typedef unsigned long long u64;

// Global accumulator. Zero-initialized at module load; fin_k resets it after
// each launch so CUDA-graph replays stay deterministic.
static __device__ double g_acc = 0.0;

__device__ __forceinline__ float frsqrt_(float x) {
    float r; asm("rsqrt.approx.f32 %0, %1;" : "=f"(r) : "f"(x)); return r;
}
__device__ __forceinline__ float fsqrt_(float x) {
    float r; asm("sqrt.approx.f32 %0, %1;" : "=f"(r) : "f"(x)); return r;
}
__device__ __forceinline__ float frcp_(float x) {
    float r; asm("rcp.approx.f32 %0, %1;" : "=f"(r) : "f"(x)); return r;
}

// ---- packed f32x2 helpers (Blackwell FFMA2 path; ptxas never emits these) ----
__device__ __forceinline__ u64 pk(float lo, float hi) {
    u64 r; asm("mov.b64 %0, {%1, %2};" : "=l"(r) : "f"(lo), "f"(hi)); return r;
}
__device__ __forceinline__ void upk(u64 v, float& lo, float& hi) {
    asm("mov.b64 {%0, %1}, %2;" : "=f"(lo), "=f"(hi) : "l"(v));
}
__device__ __forceinline__ u64 f2fma(u64 a, u64 b, u64 c) {
    u64 r; asm("fma.rn.f32x2 %0, %1, %2, %3;" : "=l"(r) : "l"(a), "l"(b), "l"(c)); return r;
}
__device__ __forceinline__ u64 f2mul(u64 a, u64 b) {
    u64 r; asm("mul.rn.f32x2 %0, %1, %2;" : "=l"(r) : "l"(a), "l"(b)); return r;
}
__device__ __forceinline__ u64 f2add(u64 a, u64 b) {
    u64 r; asm("add.rn.f32x2 %0, %1, %2;" : "=l"(r) : "l"(a), "l"(b)); return r;
}
// load two packed fields (2k, 2k+1) for one m-pair from shared
__device__ __forceinline__ void lds2(uint32_t saddr, u64& a, u64& b) {
    asm volatile("ld.shared.v2.u64 {%0, %1}, [%2];" : "=l"(a), "=l"(b) : "r"(saddr));
}

// Quaternion (qw,qx,qy,qz), UNNORMALIZED (matches reference), row-major R.
__device__ __forceinline__ void quat_to_R(float qw, float qx, float qy, float qz,
                                          float* R) {
    float xx = qx * qx, yy = qy * qy, zz = qz * qz;
    float xy = qx * qy, xz = qx * qz, yz = qy * qz;
    float wx = qw * qx, wy = qw * qy, wz = qw * qz;
    R[0] = 1.0f - 2.0f * yy - 2.0f * zz;
    R[1] = 2.0f * xy - 2.0f * wz;
    R[2] = 2.0f * xz + 2.0f * wy;
    R[3] = 2.0f * xy + 2.0f * wz;
    R[4] = 1.0f - 2.0f * xx - 2.0f * zz;
    R[5] = 2.0f * yz - 2.0f * wx;
    R[6] = 2.0f * xz - 2.0f * wy;
    R[7] = 2.0f * yz + 2.0f * wx;
    R[8] = 1.0f - 2.0f * xx - 2.0f * yy;
}

// Shared field order (per m-pair, pair-interleaved SoA):
// 0 -x, 1 -y, 2 -z, 3 R0, 4 R3, 5 R6, 6 R1, 7 R4, 8 R7,
// 9 R2, 10 R5, 11 R8, 12 sx^2, 13 sy^2, 14 sz^2, 15 -vx, 16 -vy, 17 -vz
// Layout: pair p occupies 36 floats; field f half h at p*36 + (f>>1)*4 + (f&1)*2 + h.

__global__ __launch_bounds__(TILE, 3)
void pair_k(const float* __restrict__ xyz, const float* __restrict__ scales,
            const float* __restrict__ rot, const float* __restrict__ vel,
            int N, int T, int TP) {
    __shared__ __align__(16) float shf[TILE * 18];
    __shared__ float warp_sums[TILE / 32];

    int bx = blockIdx.x;
    int b  = bx / TP;
    int t  = bx - b * TP;
    int i = 0;
    while (t >= T - i) { t -= T - i; i++; }
    int j = i + t;

    int tid = threadIdx.x;

    // ---- stage m-tile j into shared (one point per thread) ----
    {
        int m = j * TILE + tid;
        size_t p3 = (size_t)(b * N + m) * 3;
        size_t p4 = (size_t)(b * N + m) * 4;
        float R[9];
        quat_to_R(rot[p4 + 0], rot[p4 + 1], rot[p4 + 2], rot[p4 + 3], R);
        float sx = scales[p3 + 0], sy = scales[p3 + 1], sz = scales[p3 + 2];
        float vals[18];
        vals[0]  = -xyz[p3 + 0]; vals[1]  = -xyz[p3 + 1]; vals[2]  = -xyz[p3 + 2];
        vals[3]  = R[0]; vals[4]  = R[3]; vals[5]  = R[6];
        vals[6]  = R[1]; vals[7]  = R[4]; vals[8]  = R[7];
        vals[9]  = R[2]; vals[10] = R[5]; vals[11] = R[8];
        vals[12] = sx * sx; vals[13] = sy * sy; vals[14] = sz * sz;
        vals[15] = -vel[p3 + 0]; vals[16] = -vel[p3 + 1]; vals[17] = -vel[p3 + 2];
        int p = tid >> 1, h = tid & 1;
        float* dstb = &shf[p * 36];
        #pragma unroll
        for (int f = 0; f < 18; f++)
            dstb[(f >> 1) * 4 + (f & 1) * 2 + h] = vals[f];
    }

    // ---- own point n -> packed broadcast constants ----
    u64 xn2, yn2, zn2, vxn2, vyn2, vzn2, s2xn2, s2yn2, s2zn2;
    u64 Rn2[9];
    {
        int n = i * TILE + tid;
        size_t p3 = (size_t)(b * N + n) * 3;
        size_t p4 = (size_t)(b * N + n) * 4;
        float Rn[9];
        quat_to_R(rot[p4 + 0], rot[p4 + 1], rot[p4 + 2], rot[p4 + 3], Rn);
        float xn = xyz[p3 + 0], yn = xyz[p3 + 1], zn = xyz[p3 + 2];
        float sx = scales[p3 + 0], sy = scales[p3 + 1], sz = scales[p3 + 2];
        float vx = vel[p3 + 0], vy = vel[p3 + 1], vz = vel[p3 + 2];
        xn2 = pk(xn, xn); yn2 = pk(yn, yn); zn2 = pk(zn, zn);
        vxn2 = pk(vx, vx); vyn2 = pk(vy, vy); vzn2 = pk(vz, vz);
        s2xn2 = pk(sx * sx, sx * sx);
        s2yn2 = pk(sy * sy, sy * sy);
        s2zn2 = pk(sz * sz, sz * sz);
        #pragma unroll
        for (int k = 0; k < 9; k++) Rn2[k] = pk(Rn[k], Rn[k]);
    }
    const u64 eps2 = pk(1e-8f, 1e-8f);

    __syncthreads();

    uint32_t sbase = (uint32_t)__cvta_generic_to_shared(shf);
    float acc = 0.0f;

    #pragma unroll 2
    for (int it = 0; it < TILE / 2; it++) {
        uint32_t sa = sbase + it * 144;   // 36 floats per pair block

        u64 ngx, ngy, ngz, r0m, r3m, r6m, r1m, r4m, r7m, r2m, r5m, r8m;
        u64 s2xm, s2ym, s2zm, nvx, nvy, nvz;
        lds2(sa +   0, ngx, ngy);
        lds2(sa +  16, ngz, r0m);
        lds2(sa +  32, r3m, r6m);

        u64 dx = f2add(xn2, ngx);
        u64 dy = f2add(yn2, ngy);
        u64 dz = f2add(zn2, ngz);
        u64 dd = f2fma(dx, dx, eps2);
        dd = f2fma(dy, dy, dd);
        dd = f2fma(dz, dz, dd);

        lds2(sa +  48, r1m, r4m);
        lds2(sa +  64, r7m, r2m);
        lds2(sa +  80, r5m, r8m);

        // b path: diff @ R_m (columns), scaled by scales_n^2
        u64 b0 = f2mul(dx, r0m); b0 = f2fma(dy, r3m, b0); b0 = f2fma(dz, r6m, b0);
        u64 b1 = f2mul(dx, r1m); b1 = f2fma(dy, r4m, b1); b1 = f2fma(dz, r7m, b1);
        u64 b2 = f2mul(dx, r2m); b2 = f2fma(dy, r5m, b2); b2 = f2fma(dz, r8m, b2);
        u64 s2v = f2mul(f2mul(b0, b0), s2xn2);
        s2v = f2fma(f2mul(b1, b1), s2yn2, s2v);
        s2v = f2fma(f2mul(b2, b2), s2zn2, s2v);

        lds2(sa +  96, s2xm, s2ym);
        lds2(sa + 112, s2zm, nvx);
        lds2(sa + 128, nvy, nvz);

        // a path: diff @ R_n (columns), scaled by scales_m^2
        u64 t0 = f2mul(dx, Rn2[0]); t0 = f2fma(dy, Rn2[3], t0); t0 = f2fma(dz, Rn2[6], t0);
        u64 t1 = f2mul(dx, Rn2[1]); t1 = f2fma(dy, Rn2[4], t1); t1 = f2fma(dz, Rn2[7], t1);
        u64 t2 = f2mul(dx, Rn2[2]); t2 = f2fma(dy, Rn2[5], t2); t2 = f2fma(dz, Rn2[8], t2);
        u64 s1v = f2mul(f2mul(t0, t0), s2xm);
        s1v = f2fma(f2mul(t1, t1), s2ym, s1v);
        s1v = f2fma(f2mul(t2, t2), s2zm, s1v);

        // w = (v_n - v_m) . diff
        u64 rx = f2add(vxn2, nvx);
        u64 ry = f2add(vyn2, nvy);
        u64 rz = f2add(vzn2, nvz);
        u64 w = f2mul(rx, dx);
        w = f2fma(ry, dy, w);
        w = f2fma(rz, dz, w);

        float ddA, ddB, s1A, s1B, s2A, s2B, wA, wB;
        upk(dd, ddA, ddB);
        upk(s1v, s1A, s1B);
        upk(s2v, s2A, s2B);
        upk(w, wA, wB);

        // half A
        {
            float inv = frsqrt_(ddA);
            float rr = fmaxf(fsqrt_(s1A) + fsqrt_(s2A) - ddA, 0.0f);
            float ov = rr * inv;
            float rc = frcp_(fmaf(0.1f, ov, 1.0f));
            float spec = ov * ov * rc;
            float va = wA * inv;
            float hn = fmaxf(-va, 0.0f);
            acc += spec + 0.1f * ov * hn;
        }
        // half B
        {
            float inv = frsqrt_(ddB);
            float rr = fmaxf(fsqrt_(s1B) + fsqrt_(s2B) - ddB, 0.0f);
            float ov = rr * inv;
            float rc = frcp_(fmaf(0.1f, ov, 1.0f));
            float spec = ov * ov * rc;
            float va = wB * inv;
            float hn = fmaxf(-va, 0.0f);
            acc += spec + 0.1f * ov * hn;
        }
    }

    // ---- block reduction ----
    #pragma unroll
    for (int off = 16; off > 0; off >>= 1)
        acc += __shfl_down_sync(0xFFFFFFFFu, acc, off);
    if ((tid & 31) == 0) warp_sums[tid >> 5] = acc;
    __syncthreads();
    if (tid == 0) {
        float s = 0.0f;
        #pragma unroll
        for (int w = 0; w < TILE / 32; w++) s += warp_sums[w];
        float weight = (i == j) ? 1.0f : 2.0f;
        atomicAdd(&g_acc, (double)(s * weight));
    }
}

__global__ void fin_k(float* out, double norm) {
    out[0] = (float)(g_acc / norm);
    g_acc = 0.0;   // reset for next (graph-replayed) launch
}

extern "C" void kernel_launch(void* const* d_in, const int* in_sizes, int n_in,
                              void* d_out, int out_size) {
    const float* xyz    = (const float*)d_in[0];
    const float* scales = (const float*)d_in[1];
    const float* rot    = (const float*)d_in[2];
    const float* vel    = (const float*)d_in[3];

    int BN = in_sizes[2] / 4;   // rotations: B*N*4
    int N  = 2048;
    if (BN % N != 0) N = BN;
    int B  = BN / N;

    int T  = N / TILE;
    int TP = T * (T + 1) / 2;

    pair_k<<<B * TP, TILE>>>(xyz, scales, rot, vel, N, T, TP);
    fin_k<<<1, 1>>>((float*)d_out, (double)B * (double)N * (double)N);
}

// round 3
// speedup vs baseline: 1.2019x; 1.0083x over previous
#include <cuda_runtime.h>
#include <cstdint>

#define TILE 64

typedef unsigned long long u64;

// Global accumulator + completion counter. Zero-initialized at module load;
// the last finishing block resets both so CUDA-graph replays are deterministic.
static __device__ double g_acc = 0.0;
static __device__ unsigned int g_count = 0;

__device__ __forceinline__ float frsqrt_(float x) {
    float r; asm("rsqrt.approx.f32 %0, %1;" : "=f"(r) : "f"(x)); return r;
}
__device__ __forceinline__ float fsqrt_(float x) {
    float r; asm("sqrt.approx.f32 %0, %1;" : "=f"(r) : "f"(x)); return r;
}
__device__ __forceinline__ float frcp_(float x) {
    float r; asm("rcp.approx.f32 %0, %1;" : "=f"(r) : "f"(x)); return r;
}

// ---- packed f32x2 helpers (Blackwell FFMA2 path; ptxas never emits these) ----
__device__ __forceinline__ u64 pk(float lo, float hi) {
    u64 r; asm("mov.b64 %0, {%1, %2};" : "=l"(r) : "f"(lo), "f"(hi)); return r;
}
__device__ __forceinline__ void upk(u64 v, float& lo, float& hi) {
    asm("mov.b64 {%0, %1}, %2;" : "=f"(lo), "=f"(hi) : "l"(v));
}
__device__ __forceinline__ u64 f2fma(u64 a, u64 b, u64 c) {
    u64 r; asm("fma.rn.f32x2 %0, %1, %2, %3;" : "=l"(r) : "l"(a), "l"(b), "l"(c)); return r;
}
__device__ __forceinline__ u64 f2mul(u64 a, u64 b) {
    u64 r; asm("mul.rn.f32x2 %0, %1, %2;" : "=l"(r) : "l"(a), "l"(b)); return r;
}
__device__ __forceinline__ u64 f2add(u64 a, u64 b) {
    u64 r; asm("add.rn.f32x2 %0, %1, %2;" : "=l"(r) : "l"(a), "l"(b)); return r;
}
__device__ __forceinline__ void lds2(uint32_t saddr, u64& a, u64& b) {
    asm volatile("ld.shared.v2.u64 {%0, %1}, [%2];" : "=l"(a), "=l"(b) : "r"(saddr));
}

// Quaternion (qw,qx,qy,qz), UNNORMALIZED (matches reference), row-major R.
__device__ __forceinline__ void quat_to_R(float qw, float qx, float qy, float qz,
                                          float* R) {
    float xx = qx * qx, yy = qy * qy, zz = qz * qz;
    float xy = qx * qy, xz = qx * qz, yz = qy * qz;
    float wx = qw * qx, wy = qw * qy, wz = qw * qz;
    R[0] = 1.0f - 2.0f * yy - 2.0f * zz;
    R[1] = 2.0f * xy - 2.0f * wz;
    R[2] = 2.0f * xz + 2.0f * wy;
    R[3] = 2.0f * xy + 2.0f * wz;
    R[4] = 1.0f - 2.0f * xx - 2.0f * zz;
    R[5] = 2.0f * yz - 2.0f * wx;
    R[6] = 2.0f * xz - 2.0f * wy;
    R[7] = 2.0f * yz + 2.0f * wx;
    R[8] = 1.0f - 2.0f * xx - 2.0f * yy;
}

// Shared field order per m-pair (pair-interleaved SoA, 36 floats/pair):
// 0 -x, 1 -y, 2 -z, 3 R0, 4 R3, 5 R6, 6 R1, 7 R4, 8 R7,
// 9 R2, 10 R5, 11 R8, 12 sx^2, 13 sy^2, 14 sz^2, 15 -vx, 16 -vy, 17 -vz
// field f, half h at p*36 + (f>>1)*4 + (f&1)*2 + h.

__global__ __launch_bounds__(TILE, 8)
void pair_k(const float* __restrict__ xyz, const float* __restrict__ scales,
            const float* __restrict__ rot, const float* __restrict__ vel,
            float* __restrict__ out, double inv_norm,
            int N, int T, int TP) {
    __shared__ __align__(16) float shf[TILE * 18];
    __shared__ float warp_sums[TILE / 32];

    int bx = blockIdx.x;
    int b  = bx / TP;
    int t  = bx - b * TP;
    int i = 0;
    while (t >= T - i) { t -= T - i; i++; }
    int j = i + t;

    int tid = threadIdx.x;

    // ---- stage m-tile j into shared (one point per thread) ----
    {
        int m = j * TILE + tid;
        size_t p3 = (size_t)(b * N + m) * 3;
        size_t p4 = (size_t)(b * N + m) * 4;
        float R[9];
        quat_to_R(rot[p4 + 0], rot[p4 + 1], rot[p4 + 2], rot[p4 + 3], R);
        float sx = scales[p3 + 0], sy = scales[p3 + 1], sz = scales[p3 + 2];
        float vals[18];
        vals[0]  = -xyz[p3 + 0]; vals[1]  = -xyz[p3 + 1]; vals[2]  = -xyz[p3 + 2];
        vals[3]  = R[0]; vals[4]  = R[3]; vals[5]  = R[6];
        vals[6]  = R[1]; vals[7]  = R[4]; vals[8]  = R[7];
        vals[9]  = R[2]; vals[10] = R[5]; vals[11] = R[8];
        vals[12] = sx * sx; vals[13] = sy * sy; vals[14] = sz * sz;
        vals[15] = -vel[p3 + 0]; vals[16] = -vel[p3 + 1]; vals[17] = -vel[p3 + 2];
        int p = tid >> 1, h = tid & 1;
        float* dstb = &shf[p * 36];
        #pragma unroll
        for (int f = 0; f < 18; f++)
            dstb[(f >> 1) * 4 + (f & 1) * 2 + h] = vals[f];
    }

    // ---- own point n -> packed broadcast constants ----
    u64 xn2, yn2, zn2, vxn2, vyn2, vzn2, s2xn2, s2yn2, s2zn2;
    u64 Rn2[9];
    {
        int n = i * TILE + tid;
        size_t p3 = (size_t)(b * N + n) * 3;
        size_t p4 = (size_t)(b * N + n) * 4;
        float Rn[9];
        quat_to_R(rot[p4 + 0], rot[p4 + 1], rot[p4 + 2], rot[p4 + 3], Rn);
        float xn = xyz[p3 + 0], yn = xyz[p3 + 1], zn = xyz[p3 + 2];
        float sx = scales[p3 + 0], sy = scales[p3 + 1], sz = scales[p3 + 2];
        float vx = vel[p3 + 0], vy = vel[p3 + 1], vz = vel[p3 + 2];
        xn2 = pk(xn, xn); yn2 = pk(yn, yn); zn2 = pk(zn, zn);
        vxn2 = pk(vx, vx); vyn2 = pk(vy, vy); vzn2 = pk(vz, vz);
        s2xn2 = pk(sx * sx, sx * sx);
        s2yn2 = pk(sy * sy, sy * sy);
        s2zn2 = pk(sz * sz, sz * sz);
        #pragma unroll
        for (int k = 0; k < 9; k++) Rn2[k] = pk(Rn[k], Rn[k]);
    }
    const u64 eps2 = pk(1e-8f, 1e-8f);

    __syncthreads();

    uint32_t sbase = (uint32_t)__cvta_generic_to_shared(shf);
    float acc = 0.0f;

    #pragma unroll 2
    for (int it = 0; it < TILE / 2; it++) {
        uint32_t sa = sbase + it * 144;   // 36 floats per pair block

        u64 ngx, ngy, ngz, r0m, r3m, r6m, r1m, r4m, r7m, r2m, r5m, r8m;
        u64 s2xm, s2ym, s2zm, nvx, nvy, nvz;
        lds2(sa +   0, ngx, ngy);
        lds2(sa +  16, ngz, r0m);
        lds2(sa +  32, r3m, r6m);

        u64 dx = f2add(xn2, ngx);
        u64 dy = f2add(yn2, ngy);
        u64 dz = f2add(zn2, ngz);
        u64 dd = f2fma(dx, dx, eps2);
        dd = f2fma(dy, dy, dd);
        dd = f2fma(dz, dz, dd);

        lds2(sa +  48, r1m, r4m);
        lds2(sa +  64, r7m, r2m);
        lds2(sa +  80, r5m, r8m);

        // b path: diff @ R_m (columns), scaled by scales_n^2
        u64 b0 = f2mul(dx, r0m); b0 = f2fma(dy, r3m, b0); b0 = f2fma(dz, r6m, b0);
        u64 b1 = f2mul(dx, r1m); b1 = f2fma(dy, r4m, b1); b1 = f2fma(dz, r7m, b1);
        u64 b2 = f2mul(dx, r2m); b2 = f2fma(dy, r5m, b2); b2 = f2fma(dz, r8m, b2);
        u64 s2v = f2mul(f2mul(b0, b0), s2xn2);
        s2v = f2fma(f2mul(b1, b1), s2yn2, s2v);
        s2v = f2fma(f2mul(b2, b2), s2zn2, s2v);

        lds2(sa +  96, s2xm, s2ym);
        lds2(sa + 112, s2zm, nvx);
        lds2(sa + 128, nvy, nvz);

        // a path: diff @ R_n (columns), scaled by scales_m^2
        u64 t0 = f2mul(dx, Rn2[0]); t0 = f2fma(dy, Rn2[3], t0); t0 = f2fma(dz, Rn2[6], t0);
        u64 t1 = f2mul(dx, Rn2[1]); t1 = f2fma(dy, Rn2[4], t1); t1 = f2fma(dz, Rn2[7], t1);
        u64 t2 = f2mul(dx, Rn2[2]); t2 = f2fma(dy, Rn2[5], t2); t2 = f2fma(dz, Rn2[8], t2);
        u64 s1v = f2mul(f2mul(t0, t0), s2xm);
        s1v = f2fma(f2mul(t1, t1), s2ym, s1v);
        s1v = f2fma(f2mul(t2, t2), s2zm, s1v);

        // w = (v_n - v_m) . diff
        u64 rx = f2add(vxn2, nvx);
        u64 ry = f2add(vyn2, nvy);
        u64 rz = f2add(vzn2, nvz);
        u64 w = f2mul(rx, dx);
        w = f2fma(ry, dy, w);
        w = f2fma(rz, dz, w);

        float ddA, ddB, s1A, s1B, s2A, s2B, wA, wB;
        upk(dd, ddA, ddB);
        upk(s1v, s1A, s1B);
        upk(s2v, s2A, s2B);
        upk(w, wA, wB);

        // half A
        {
            float inv = frsqrt_(ddA);
            float rr = fmaxf(fsqrt_(s1A) + fsqrt_(s2A) - ddA, 0.0f);
            float ov = rr * inv;
            float rc = frcp_(fmaf(0.1f, ov, 1.0f));
            float spec = ov * ov * rc;
            float va = wA * inv;
            float hn = fmaxf(-va, 0.0f);
            acc += spec + 0.1f * ov * hn;
        }
        // half B
        {
            float inv = frsqrt_(ddB);
            float rr = fmaxf(fsqrt_(s1B) + fsqrt_(s2B) - ddB, 0.0f);
            float ov = rr * inv;
            float rc = frcp_(fmaf(0.1f, ov, 1.0f));
            float spec = ov * ov * rc;
            float va = wB * inv;
            float hn = fmaxf(-va, 0.0f);
            acc += spec + 0.1f * ov * hn;
        }
    }

    // ---- block reduction ----
    #pragma unroll
    for (int off = 16; off > 0; off >>= 1)
        acc += __shfl_down_sync(0xFFFFFFFFu, acc, off);
    if ((tid & 31) == 0) warp_sums[tid >> 5] = acc;
    __syncthreads();

    if (tid == 0) {
        float s = 0.0f;
        #pragma unroll
        for (int w = 0; w < TILE / 32; w++) s += warp_sums[w];
        float weight = (i == j) ? 1.0f : 2.0f;
        atomicAdd(&g_acc, (double)(s * weight));

        // ---- last-block finalization (replaces separate fin_k launch) ----
        __threadfence();
        unsigned int done = atomicAdd(&g_count, 1u);
        if (done == gridDim.x - 1) {
            out[0] = (float)(g_acc * inv_norm);
            g_acc = 0.0;      // reset for next graph replay
            g_count = 0u;
        }
    }
}

extern "C" void kernel_launch(void* const* d_in, const int* in_sizes, int n_in,
                              void* d_out, int out_size) {
    const float* xyz    = (const float*)d_in[0];
    const float* scales = (const float*)d_in[1];
    const float* rot    = (const float*)d_in[2];
    const float* vel    = (const float*)d_in[3];

    int BN = in_sizes[2] / 4;   // rotations: B*N*4
    int N  = 2048;
    if (BN % N != 0) N = BN;
    int B  = BN / N;

    int T  = N / TILE;
    int TP = T * (T + 1) / 2;

    double inv_norm = 1.0 / ((double)B * (double)N * (double)N);
    pair_k<<<B * TP, TILE>>>(xyz, scales, rot, vel, (float*)d_out, inv_norm,
                             N, T, TP);
}